// round 14
// baseline (speedup 1.0000x reference)
#include <cuda_runtime.h>
#include <cuda_bf16.h>
#include <math.h>
#include <stdint.h>

#define BATCH_N   4096
#define FEAT_D    512
#define NUM_AGES  100
#define AGE_PAD   128
#define EPS_F     1e-6f

#define TI 64
#define TJ 128
#define NJT (BATCH_N / TJ)                 // 32
#define NPAIR (NJT * NJT + NJT)            // 1056 main tiles
#define NU    (BATCH_N / 32)               // 128 U tiles
#define NW    (AGE_PAD / 2)                // 64 w blocks (2 ages each)
#define NPREP (BATCH_N / 8)                // 512 prep blocks
#define NPRE  (NW + NPREP)                 // 576 pre-counter target
#define KC 64
#define NCHUNK (FEAT_D / KC)               // 8
#define NSTAGE 3

#define STAGE_MAIN 24576                   // Zi 8KB + Zj 16KB
#define STAGE_U    20480                   // Zi 4KB + Wa 16KB
#define META 2048
#define SMEM_DYN (1024 + META + NSTAGE * STAGE_MAIN)    // 76800 -> 3 CTAs/SM

#define SW128(o) ((o) ^ (((o) >> 3) & 0x70))

// ---------------- device scratch (zero-init; self-cleaned every run) ----------------
__device__ __nv_bfloat16 g_zb[BATCH_N * FEAT_D];
__device__ __nv_bfloat16 g_wab[AGE_PAD * FEAT_D];
__device__ float  g_U[AGE_PAD * BATCH_N];
__device__ float  g_sq[BATCH_N];
__device__ int    g_ages[BATCH_N];
__device__ int    g_perm[BATCH_N];
__device__ double g_acc;
__device__ int    g_cnt;
__device__ int    g_cnt_u;
__device__ int    g_cnt_pre;
__device__ int    g_flag_sort;

// ---------------- PTX helpers ----------------
static __device__ __forceinline__ void ldsm_x4(uint32_t (&r)[4], uint32_t addr) {
    asm volatile("ldmatrix.sync.aligned.m8n8.x4.shared.b16 {%0,%1,%2,%3}, [%4];"
                 : "=r"(r[0]), "=r"(r[1]), "=r"(r[2]), "=r"(r[3]) : "r"(addr));
}
static __device__ __forceinline__ void mma_bf16(float (&c)[4], const uint32_t (&a)[4],
                                                const uint32_t b0, const uint32_t b1) {
    asm volatile(
        "mma.sync.aligned.m16n8k16.row.col.f32.bf16.bf16.f32 "
        "{%0,%1,%2,%3}, {%4,%5,%6,%7}, {%8,%9}, {%0,%1,%2,%3};"
        : "+f"(c[0]), "+f"(c[1]), "+f"(c[2]), "+f"(c[3])
        : "r"(a[0]), "r"(a[1]), "r"(a[2]), "r"(a[3]), "r"(b0), "r"(b1));
}
static __device__ __forceinline__ void cp16(uint32_t dst, const void* src) {
    asm volatile("cp.async.cg.shared.global [%0], [%1], 16;" :: "r"(dst), "l"(src) : "memory");
}

// -------- 3-stage pipeline core: 8 warps (2m x 4n), prefetch depth 2 --------
#define PIPELINE_GEMM(MTILES, SBYTES, AOFF)                                         \
    load_stage(0);                                                                  \
    load_stage(1);                                                                  \
    _Pragma("unroll 1")                                                             \
    for (int c = 0; c < NCHUNK; ++c) {                                              \
        if (c == NCHUNK - 1) asm volatile("cp.async.wait_group 0;" ::: "memory");   \
        else                 asm volatile("cp.async.wait_group 1;" ::: "memory");   \
        __syncthreads();                                                            \
        if (c + 2 < NCHUNK) load_stage(c + 2);                                      \
        const uint32_t st = stg0 + (uint32_t)(c % NSTAGE) * (SBYTES);               \
        const uint32_t zi = st, bj = st + (AOFF);                                   \
        _Pragma("unroll")                                                           \
        for (int kb = 0; kb < KC; kb += 16) {                                       \
            uint32_t a[MTILES][4];                                                  \
            _Pragma("unroll")                                                       \
            for (int mt = 0; mt < MTILES; ++mt) {                                   \
                int row = wm * (16 * MTILES) + mt * 16 + lr + (q8 & 1) * 8;         \
                int col = kb + (q8 >> 1) * 8;                                       \
                ldsm_x4(a[mt], zi + SW128((uint32_t)(row * 128 + col * 2)));        \
            }                                                                       \
            uint32_t bz[4][2];                                                      \
            _Pragma("unroll")                                                       \
            for (int p = 0; p < 2; ++p) {                                           \
                int row = wn * 32 + p * 16 + lr + (q8 >> 1) * 8;                    \
                int col = kb + (q8 & 1) * 8;                                        \
                uint32_t rz[4];                                                     \
                ldsm_x4(rz, bj + SW128((uint32_t)(row * 128 + col * 2)));           \
                bz[2 * p][0] = rz[0]; bz[2 * p][1] = rz[1];                         \
                bz[2 * p + 1][0] = rz[2]; bz[2 * p + 1][1] = rz[3];                 \
            }                                                                       \
            _Pragma("unroll")                                                       \
            for (int mt = 0; mt < MTILES; ++mt)                                     \
                _Pragma("unroll")                                                   \
                for (int nt = 0; nt < 4; ++nt)                                      \
                    mma_bf16(cg[mt][nt], a[mt], bz[nt][0], bz[nt][1]);              \
        }                                                                           \
    }

// ================= single fused kernel =================
__global__ __launch_bounds__(256, 3) void k_fused(float* __restrict__ out,
                                                  const float* __restrict__ z,
                                                  const void* __restrict__ ages_raw,
                                                  const float* __restrict__ proxies) {
    extern __shared__ char smem_raw[];
    uint32_t sbase;
    asm("{ .reg .u64 t; cvta.to.shared.u64 t, %1; cvt.u32.u64 %0, t; }"
        : "=r"(sbase) : "l"(smem_raw));
    const uint32_t abase = (sbase + 1023u) & ~1023u;
    char* ab = smem_raw + (abase - sbase);
    const uint32_t stg0 = abase + META;

    const int bid  = blockIdx.x;
    const int tid  = threadIdx.x;
    const int lane = tid & 31;
    const int wid  = tid >> 5;
    const int wm   = wid >> 2;
    const int wn   = wid & 3;
    const int q8 = lane >> 3;
    const int lr = lane & 7;

    // ================= stage 0: sort (bid 0) =================
    if (bid == 0) {
        int* s_hist = (int*)(ab);            // 100 ints
        int* s_off  = (int*)(ab + 512);      // 100 ints
        __shared__ int s_ok[2];
        __shared__ int s_is64;
        if (tid < 64) {
            long long v = ((const long long*)ages_raw)[tid];
            int ok = (v >= 0 && v < NUM_AGES) ? 1 : 0;
            unsigned m = __ballot_sync(0xFFFFFFFFu, ok);
            if ((tid & 31) == 0) s_ok[tid >> 5] = (m == 0xFFFFFFFFu);
        }
        if (tid < NUM_AGES) s_hist[tid] = 0;
        __syncthreads();
        if (tid == 0) s_is64 = s_ok[0] & s_ok[1];
        __syncthreads();
        const int is64 = s_is64;

        for (int i = tid; i < BATCH_N; i += 256) {
            int a = is64 ? (int)((const long long*)ages_raw)[i]
                         : ((const int*)ages_raw)[i];
            atomicAdd(&s_hist[a], 1);
        }
        __syncthreads();
        if (tid == 0) {
            int run = 0;
            for (int bb = 0; bb < NUM_AGES; ++bb) { s_off[bb] = run; run += s_hist[bb]; }
        }
        __syncthreads();
        for (int i = tid; i < BATCH_N; i += 256) {
            int a = is64 ? (int)((const long long*)ages_raw)[i]
                         : ((const int*)ages_raw)[i];
            int pos = atomicAdd(&s_off[a], 1);
            g_perm[pos] = i;
            g_ages[pos] = a;
        }
        __syncthreads();
        if (tid == 0) {
            __threadfence();
            *(volatile int*)&g_flag_sort = 1;
        }
        return;
    }

    // ================= stage 1: per-age w (bids 1..NW) =================
    if (bid <= NW) {
        const int a  = (bid - 1) * 2 + (tid >> 7);   // 0..127
        const int tt = tid & 127;
        const int ac = min(a, NUM_AGES - 1);
        const int an = min(ac + 1, NUM_AGES - 1);
        const int ap = max(ac - 1, 0);
        float4 c4 = ((const float4*)(proxies + (size_t)ac * FEAT_D))[tt];
        float4 n4 = ((const float4*)(proxies + (size_t)an * FEAT_D))[tt];
        float4 p4 = ((const float4*)(proxies + (size_t)ap * FEAT_D))[tt];
        float df[4] = {n4.x - c4.x, n4.y - c4.y, n4.z - c4.z, n4.w - c4.w};
        float db[4] = {p4.x - c4.x, p4.y - c4.y, p4.z - c4.z, p4.w - c4.w};

        float nf2 = 0.f, nb2 = 0.f;
#pragma unroll
        for (int q = 0; q < 4; ++q) { nf2 += df[q] * df[q]; nb2 += db[q] * db[q]; }
#pragma unroll
        for (int o = 16; o; o >>= 1) {
            nf2 += __shfl_xor_sync(0xFFFFFFFFu, nf2, o);
            nb2 += __shfl_xor_sync(0xFFFFFFFFu, nb2, o);
        }
        __shared__ float sf[8], sb[8];
        if ((tid & 31) == 0) { sf[wid] = nf2; sb[wid] = nb2; }
        __syncthreads();
        const int w0 = (tid >> 7) * 4;
        nf2 = sf[w0] + sf[w0 + 1] + sf[w0 + 2] + sf[w0 + 3];
        nb2 = sb[w0] + sb[w0 + 1] + sb[w0 + 2] + sb[w0 + 3];
        const float rf = 1.f / (sqrtf(nf2) + EPS_F);
        const float rb = 1.f / (sqrtf(nb2) + EPS_F);

        uint2 u = make_uint2(0u, 0u);
        if (a < NUM_AGES) {
            __nv_bfloat162 w0v = __floats2bfloat162_rn(db[0] * rb - df[0] * rf,
                                                       db[1] * rb - df[1] * rf);
            __nv_bfloat162 w1v = __floats2bfloat162_rn(db[2] * rb - df[2] * rf,
                                                       db[3] * rb - df[3] * rf);
            u.x = *(uint32_t*)&w0v;
            u.y = *(uint32_t*)&w1v;
        }
        ((uint2*)(g_wab + (size_t)a * FEAT_D))[tt] = u;
        __syncthreads();
        if (tid == 0) {
            __threadfence();
            atomicAdd(&g_cnt_pre, 1);
        }
        return;
    }

    // ================= stage 2: prep (bids NW+1 .. NW+NPREP) =================
    if (bid <= NW + NPREP) {
        if (tid == 0) {
            while (*(volatile int*)&g_flag_sort == 0) __nanosleep(32);
            __threadfence();
        }
        __syncthreads();

        const int r = tid >> 5;
        const int l = tid & 31;
        const int j = (bid - 1 - NW) * 8 + r;
        const int orig = g_perm[j];
        const float4* zr = (const float4*)(z + (size_t)orig * FEAT_D);
        uint2* dst = (uint2*)(g_zb + (size_t)j * FEAT_D);
        float sq = 0.f;
#pragma unroll
        for (int q = 0; q < 4; ++q) {
            float4 v = zr[l + q * 32];
            __nv_bfloat162 p0 = __floats2bfloat162_rn(v.x, v.y);
            __nv_bfloat162 p1 = __floats2bfloat162_rn(v.z, v.w);
            uint2 u;
            u.x = *(uint32_t*)&p0;
            u.y = *(uint32_t*)&p1;
            dst[l + q * 32] = u;
            sq += v.x * v.x + v.y * v.y + v.z * v.z + v.w * v.w;
        }
#pragma unroll
        for (int o = 16; o; o >>= 1) sq += __shfl_xor_sync(0xFFFFFFFFu, sq, o);
        if (l == 0) g_sq[j] = sq;
        __syncthreads();
        if (tid == 0) {
            __threadfence();
            atomicAdd(&g_cnt_pre, 1);
        }
        return;
    }

    // ================= stage 3: U tiles (next NU bids) =================
    if (bid <= NW + NPREP + NU) {
        if (tid == 0) {
            while (*(volatile int*)&g_cnt_pre < NPRE) __nanosleep(32);
            __threadfence();
        }
        __syncthreads();

        const int i0 = (bid - 1 - NW - NPREP) * 32;

        auto load_stage = [&](int c) {
            uint32_t st = stg0 + (uint32_t)(c % NSTAGE) * STAGE_U;
            int k0 = c * KC;
            {
                int u = tid;
                int row = u >> 3, un = u & 7;
                cp16(st + SW128((uint32_t)(u * 16)),
                     g_zb + (size_t)(i0 + row) * FEAT_D + k0 + un * 8);
            }
#pragma unroll
            for (int q = 0; q < 4; ++q) {
                int u = tid + q * 256;
                int row = u >> 3, un = u & 7;
                cp16(st + 4096 + SW128((uint32_t)(u * 16)),
                     g_wab + (size_t)row * FEAT_D + k0 + un * 8);
            }
            asm volatile("cp.async.commit_group;" ::: "memory");
        };

        float cg[1][4][4] = {};
        PIPELINE_GEMM(1, STAGE_U, 4096)

        const int g  = lane >> 2;
        const int tg = lane & 3;
        {
            int r0 = i0 + wm * 16 + g;
#pragma unroll
            for (int nt = 0; nt < 4; ++nt) {
                int a0 = wn * 32 + nt * 8 + tg * 2;
#pragma unroll
                for (int h = 0; h < 2; ++h) {
                    g_U[(size_t)(a0 + h) * BATCH_N + r0]     = cg[0][nt][h];
                    g_U[(size_t)(a0 + h) * BATCH_N + r0 + 8] = cg[0][nt][2 + h];
                }
            }
        }
        __syncthreads();
        if (tid == 0) {
            __threadfence();
            atomicAdd(&g_cnt_u, 1);
        }
        return;
    }

    // ================= stage 4: main G tiles =================
    if (tid == 0) {
        while (*(volatile int*)&g_cnt_pre < NPRE) __nanosleep(32);
        __threadfence();
    }
    __syncthreads();

    float* s_sqi  = (float*)(ab);
    int*   s_agi  = (int*)(ab + 256);
    float* s_sqj  = (float*)(ab + 512);
    float* s_dwj  = (float*)(ab + 1024);
    int*   s_agej = (int*)(ab + 1536);
    float* s_red  = (float*)(ab + META);

    int b = bid - 1 - NW - NPREP - NU;
    int J = (int)((sqrtf(4.0f * (float)b + 1.0f) - 1.0f) * 0.5f);
    while ((J + 1) * (J + 1) + (J + 1) <= b) ++J;
    while (J * J + J > b) --J;
    const int I  = b - (J * J + J);
    const int i0 = I * TI;
    const int j0 = J * TJ;

    if (tid < 128) {
        int aj = g_ages[j0 + tid];
        s_agej[tid] = aj;
        s_sqj[tid]  = g_sq[j0 + tid];
    } else if (tid < 192) {
        int r = tid - 128;
        s_sqi[r] = g_sq[i0 + r];
        s_agi[r] = g_ages[i0 + r];
    }

    auto load_stage = [&](int c) {
        uint32_t st = stg0 + (uint32_t)(c % NSTAGE) * STAGE_MAIN;
        int k0 = c * KC;
#pragma unroll
        for (int q = 0; q < 2; ++q) {
            int u = tid + q * 256;
            int row = u >> 3, un = u & 7;
            cp16(st + SW128((uint32_t)(u * 16)),
                 g_zb + (size_t)(i0 + row) * FEAT_D + k0 + un * 8);
        }
#pragma unroll
        for (int q = 0; q < 4; ++q) {
            int u = tid + q * 256;
            int row = u >> 3, un = u & 7;
            cp16(st + 8192 + SW128((uint32_t)(u * 16)),
                 g_zb + (size_t)(j0 + row) * FEAT_D + k0 + un * 8);
        }
        asm volatile("cp.async.commit_group;" ::: "memory");
    };

    float cg[2][4][4] = {};
    PIPELINE_GEMM(2, STAGE_MAIN, 8192)

    // ---- gate on U completion ----
    if (tid == 0) {
        while (*(volatile int*)&g_cnt_u < NU) __nanosleep(32);
        __threadfence();
    }
    __syncthreads();
    if (tid < 128) {
        s_dwj[tid] = g_U[(size_t)s_agej[tid] * BATCH_N + j0 + tid];
    }
    __syncthreads();

    // ---- epilogue ----
    const int g  = lane >> 2;
    const int tg = lane & 3;
    float sqi0[2], sqi1[2];
    int   agi0[2], agi1[2];
#pragma unroll
    for (int mt = 0; mt < 2; ++mt) {
        int r0 = wm * 32 + mt * 16 + g;
        sqi0[mt] = s_sqi[r0];      agi0[mt] = s_agi[r0];
        sqi1[mt] = s_sqi[r0 + 8];  agi1[mt] = s_agi[r0 + 8];
    }

    float lsum = 0.f;
#pragma unroll
    for (int nt = 0; nt < 4; ++nt) {
#pragma unroll
        for (int h = 0; h < 2; ++h) {
            int cj = wn * 32 + nt * 8 + tg * 2 + h;
            int   agj = s_agej[cj];
            float sqj = s_sqj[cj], dwj = s_dwj[cj];
            const float* Up = g_U + (size_t)agj * BATCH_N + i0 + wm * 32 + g;
#pragma unroll
            for (int mt = 0; mt < 2; ++mt) {
                if (agi0[mt] < agj) {
                    float G  = cg[mt][nt][h];
                    float d2 = fmaxf(sqi0[mt] + sqj - 2.f * G, 0.f);
                    float x  = __fdividef((Up[mt * 16] - dwj) * 10.0f, sqrtf(d2) + EPS_F);
                    lsum += fmaxf(x, 0.f) + __logf(1.f + __expf(-fabsf(x)));
                }
                if (agi1[mt] < agj) {
                    float G  = cg[mt][nt][2 + h];
                    float d2 = fmaxf(sqi1[mt] + sqj - 2.f * G, 0.f);
                    float x  = __fdividef((Up[mt * 16 + 8] - dwj) * 10.0f, sqrtf(d2) + EPS_F);
                    lsum += fmaxf(x, 0.f) + __logf(1.f + __expf(-fabsf(x)));
                }
            }
        }
    }

    __syncthreads();           // s_red aliases stage memory
    s_red[tid] = lsum;
    __syncthreads();
#pragma unroll
    for (int s = 128; s > 0; s >>= 1) {
        if (tid < s) s_red[tid] += s_red[tid + s];
        __syncthreads();
    }
    if (tid == 0) {
        atomicAdd(&g_acc, (double)s_red[0]);
        __threadfence();
        int n = atomicAdd(&g_cnt, 1);
        if (n == NPAIR - 1) {
            __threadfence();
            double v = atomicAdd(&g_acc, 0.0);
            out[0] = (float)(v / ((double)BATCH_N * (double)(BATCH_N - 1)));
            // self-clean all state for the next graph replay (zero-init invariant)
            g_acc = 0.0;
            g_cnt = 0;
            g_cnt_u = 0;
            g_cnt_pre = 0;
            g_flag_sort = 0;
            __threadfence();
        }
    }
}

extern "C" void kernel_launch(void* const* d_in, const int* in_sizes, int n_in,
                              void* d_out, int out_size) {
    const float* z       = (const float*)d_in[0];
    const void*  ages    = d_in[1];
    const float* proxies = (const float*)d_in[2];
    float* out = (float*)d_out;

    cudaFuncSetAttribute(k_fused, cudaFuncAttributeMaxDynamicSharedMemorySize, SMEM_DYN);

    const int grid = 1 + NW + NPREP + NU + NPAIR;   // 1761
    k_fused<<<grid, 256, SMEM_DYN>>>(out, z, ages, proxies);
}

// round 15
// speedup vs baseline: 1.2473x; 1.2473x over previous
#include <cuda_runtime.h>
#include <cuda_bf16.h>
#include <math.h>
#include <stdint.h>

#define BATCH_N   4096
#define FEAT_D    512
#define NUM_AGES  100
#define AGE_PAD   128
#define EPS_F     1e-6f

#define TI 64
#define TJ 128
#define NJT (BATCH_N / TJ)                 // 32
#define NPAIR (NJT * NJT + NJT)            // 1056 main tiles
#define NU    (BATCH_N / 32)               // 128 U tiles
#define NW    64                           // w blocks (2 ages each)
#define NPREP (BATCH_N / 8)                // 512 prep blocks
#define KC 64
#define NCHUNK (FEAT_D / KC)               // 8
#define NSTAGE 3

#define STAGE_MAIN 24576                   // Zi 8KB + Zj 16KB
#define STAGE_U    20480                   // Zi 4KB + Wa 16KB
#define META 2048
#define SMEM_MAIN (1024 + META + NSTAGE * STAGE_MAIN)   // 76800 -> 3 CTAs/SM

#define SW128(o) ((o) ^ (((o) >> 3) & 0x70))

// ---------------- device scratch ----------------
__device__ __nv_bfloat16 g_zb[BATCH_N * FEAT_D];    // ORIGINAL order bf16 z
__device__ __nv_bfloat16 g_wab[AGE_PAD * FEAT_D];   // bf16 w per age (pad zero)
__device__ float  g_U[AGE_PAD * BATCH_N];           // U[a][i_sorted]
__device__ float  g_sq[BATCH_N];                    // ORIGINAL order
__device__ int    g_ages[BATCH_N];                  // sorted ascending
__device__ int    g_perm[BATCH_N];                  // sorted pos -> original idx
__device__ double g_acc;
__device__ int    g_cnt;
__device__ int    g_cnt_u;

// ---------------- PTX helpers ----------------
static __device__ __forceinline__ void ldsm_x4(uint32_t (&r)[4], uint32_t addr) {
    asm volatile("ldmatrix.sync.aligned.m8n8.x4.shared.b16 {%0,%1,%2,%3}, [%4];"
                 : "=r"(r[0]), "=r"(r[1]), "=r"(r[2]), "=r"(r[3]) : "r"(addr));
}
static __device__ __forceinline__ void mma_bf16(float (&c)[4], const uint32_t (&a)[4],
                                                const uint32_t b0, const uint32_t b1) {
    asm volatile(
        "mma.sync.aligned.m16n8k16.row.col.f32.bf16.bf16.f32 "
        "{%0,%1,%2,%3}, {%4,%5,%6,%7}, {%8,%9}, {%0,%1,%2,%3};"
        : "+f"(c[0]), "+f"(c[1]), "+f"(c[2]), "+f"(c[3])
        : "r"(a[0]), "r"(a[1]), "r"(a[2]), "r"(a[3]), "r"(b0), "r"(b1));
}
static __device__ __forceinline__ void cp16(uint32_t dst, const void* src) {
    asm volatile("cp.async.cg.shared.global [%0], [%1], 16;" :: "r"(dst), "l"(src) : "memory");
}

// ---------------- K_pre: gate-free fusion of sort / w / prep ----------------
// bid 0: counting sort (writes g_perm, g_ages; resets counters)
// bid 1..NW: per-age w vectors
// bid NW+1..NW+NPREP: z -> bf16 + sq in ORIGINAL order (no deps)
__global__ __launch_bounds__(256) void k_pre(const float* __restrict__ z,
                                             const void* __restrict__ ages_raw,
                                             const float* __restrict__ proxies) {
    const int bid = blockIdx.x;
    const int tid = threadIdx.x;

    if (bid == 0) {
        __shared__ int s_ok[2];
        __shared__ int s_is64;
        __shared__ int s_hist[NUM_AGES];
        __shared__ int s_off[NUM_AGES];
        if (tid < 64) {
            long long v = ((const long long*)ages_raw)[tid];
            int ok = (v >= 0 && v < NUM_AGES) ? 1 : 0;
            unsigned m = __ballot_sync(0xFFFFFFFFu, ok);
            if ((tid & 31) == 0) s_ok[tid >> 5] = (m == 0xFFFFFFFFu);
        }
        if (tid == 0) {
            g_acc = 0.0;
            g_cnt = 0;
            g_cnt_u = 0;
        }
        if (tid < NUM_AGES) s_hist[tid] = 0;
        __syncthreads();
        if (tid == 0) s_is64 = s_ok[0] & s_ok[1];
        __syncthreads();
        const int is64 = s_is64;

        for (int i = tid; i < BATCH_N; i += 256) {
            int a = is64 ? (int)((const long long*)ages_raw)[i]
                         : ((const int*)ages_raw)[i];
            atomicAdd(&s_hist[a], 1);
        }
        __syncthreads();
        if (tid == 0) {
            int run = 0;
            for (int bb = 0; bb < NUM_AGES; ++bb) { s_off[bb] = run; run += s_hist[bb]; }
        }
        __syncthreads();
        for (int i = tid; i < BATCH_N; i += 256) {
            int a = is64 ? (int)((const long long*)ages_raw)[i]
                         : ((const int*)ages_raw)[i];
            int pos = atomicAdd(&s_off[a], 1);
            g_perm[pos] = i;
            g_ages[pos] = a;
        }
        return;
    }

    if (bid <= NW) {
        const int a  = (bid - 1) * 2 + (tid >> 7);   // 0..127
        const int tt = tid & 127;
        const int ac = min(a, NUM_AGES - 1);
        const int an = min(ac + 1, NUM_AGES - 1);
        const int ap = max(ac - 1, 0);
        float4 c4 = ((const float4*)(proxies + (size_t)ac * FEAT_D))[tt];
        float4 n4 = ((const float4*)(proxies + (size_t)an * FEAT_D))[tt];
        float4 p4 = ((const float4*)(proxies + (size_t)ap * FEAT_D))[tt];
        float df[4] = {n4.x - c4.x, n4.y - c4.y, n4.z - c4.z, n4.w - c4.w};
        float db[4] = {p4.x - c4.x, p4.y - c4.y, p4.z - c4.z, p4.w - c4.w};

        float nf2 = 0.f, nb2 = 0.f;
#pragma unroll
        for (int q = 0; q < 4; ++q) { nf2 += df[q] * df[q]; nb2 += db[q] * db[q]; }
#pragma unroll
        for (int o = 16; o; o >>= 1) {
            nf2 += __shfl_xor_sync(0xFFFFFFFFu, nf2, o);
            nb2 += __shfl_xor_sync(0xFFFFFFFFu, nb2, o);
        }
        __shared__ float sf[8], sb[8];
        const int wg = tid >> 5;
        if ((tid & 31) == 0) { sf[wg] = nf2; sb[wg] = nb2; }
        __syncthreads();
        const int w0 = (tid >> 7) * 4;
        nf2 = sf[w0] + sf[w0 + 1] + sf[w0 + 2] + sf[w0 + 3];
        nb2 = sb[w0] + sb[w0 + 1] + sb[w0 + 2] + sb[w0 + 3];
        const float rf = 1.f / (sqrtf(nf2) + EPS_F);
        const float rb = 1.f / (sqrtf(nb2) + EPS_F);

        uint2 u = make_uint2(0u, 0u);
        if (a < NUM_AGES) {
            __nv_bfloat162 w0v = __floats2bfloat162_rn(db[0] * rb - df[0] * rf,
                                                       db[1] * rb - df[1] * rf);
            __nv_bfloat162 w1v = __floats2bfloat162_rn(db[2] * rb - df[2] * rf,
                                                       db[3] * rb - df[3] * rf);
            u.x = *(uint32_t*)&w0v;
            u.y = *(uint32_t*)&w1v;
        }
        ((uint2*)(g_wab + (size_t)a * FEAT_D))[tt] = u;
        return;
    }

    // prep in ORIGINAL order — no dependency on the sort
    const int r = tid >> 5;
    const int l = tid & 31;
    const int j = (bid - 1 - NW) * 8 + r;
    const float4* zr = (const float4*)(z + (size_t)j * FEAT_D);
    uint2* dst = (uint2*)(g_zb + (size_t)j * FEAT_D);
    float sq = 0.f;
#pragma unroll
    for (int q = 0; q < 4; ++q) {
        float4 v = zr[l + q * 32];
        __nv_bfloat162 p0 = __floats2bfloat162_rn(v.x, v.y);
        __nv_bfloat162 p1 = __floats2bfloat162_rn(v.z, v.w);
        uint2 u;
        u.x = *(uint32_t*)&p0;
        u.y = *(uint32_t*)&p1;
        dst[l + q * 32] = u;
        sq += v.x * v.x + v.y * v.y + v.z * v.z + v.w * v.w;
    }
#pragma unroll
    for (int o = 16; o; o >>= 1) sq += __shfl_xor_sync(0xFFFFFFFFu, sq, o);
    if (l == 0) g_sq[j] = sq;
}

// -------- 3-stage pipeline core: 8 warps (2m x 4n), prefetch depth 2 --------
#define PIPELINE_GEMM(MTILES, SBYTES, AOFF)                                         \
    load_stage(0);                                                                  \
    load_stage(1);                                                                  \
    _Pragma("unroll 1")                                                             \
    for (int c = 0; c < NCHUNK; ++c) {                                              \
        if (c == NCHUNK - 1) asm volatile("cp.async.wait_group 0;" ::: "memory");   \
        else                 asm volatile("cp.async.wait_group 1;" ::: "memory");   \
        __syncthreads();                                                            \
        if (c + 2 < NCHUNK) load_stage(c + 2);                                      \
        const uint32_t st = stg0 + (uint32_t)(c % NSTAGE) * (SBYTES);               \
        const uint32_t zi = st, bj = st + (AOFF);                                   \
        _Pragma("unroll")                                                           \
        for (int kb = 0; kb < KC; kb += 16) {                                       \
            uint32_t a[MTILES][4];                                                  \
            _Pragma("unroll")                                                       \
            for (int mt = 0; mt < MTILES; ++mt) {                                   \
                int row = wm * (16 * MTILES) + mt * 16 + lr + (q8 & 1) * 8;         \
                int col = kb + (q8 >> 1) * 8;                                       \
                ldsm_x4(a[mt], zi + SW128((uint32_t)(row * 128 + col * 2)));        \
            }                                                                       \
            uint32_t bz[4][2];                                                      \
            _Pragma("unroll")                                                       \
            for (int p = 0; p < 2; ++p) {                                           \
                int row = wn * 32 + p * 16 + lr + (q8 >> 1) * 8;                    \
                int col = kb + (q8 & 1) * 8;                                        \
                uint32_t rz[4];                                                     \
                ldsm_x4(rz, bj + SW128((uint32_t)(row * 128 + col * 2)));           \
                bz[2 * p][0] = rz[0]; bz[2 * p][1] = rz[1];                         \
                bz[2 * p + 1][0] = rz[2]; bz[2 * p + 1][1] = rz[3];                 \
            }                                                                       \
            _Pragma("unroll")                                                       \
            for (int mt = 0; mt < MTILES; ++mt)                                     \
                _Pragma("unroll")                                                   \
                for (int nt = 0; nt < 4; ++nt)                                      \
                    mma_bf16(cg[mt][nt], a[mt], bz[nt][0], bz[nt][1]);              \
        }                                                                           \
    }

// ---------------- fused K2: blocks 0..NU-1 compute U; the rest do G tiles ----------------
// Loaders indirect through g_perm (row indices fixed per thread -> cached in regs).
__global__ __launch_bounds__(256, 3) void k_main(float* __restrict__ out) {
    extern __shared__ char smem_raw[];
    uint32_t sbase;
    asm("{ .reg .u64 t; cvta.to.shared.u64 t, %1; cvt.u32.u64 %0, t; }"
        : "=r"(sbase) : "l"(smem_raw));
    const uint32_t abase = (sbase + 1023u) & ~1023u;
    char* ab = smem_raw + (abase - sbase);
    const uint32_t stg0 = abase + META;

    const int tid  = threadIdx.x;
    const int lane = tid & 31;
    const int wid  = tid >> 5;
    const int wm   = wid >> 2;
    const int wn   = wid & 3;
    const int q8 = lane >> 3;
    const int lr = lane & 7;

    if (blockIdx.x < NU) {
        const int i0 = blockIdx.x * 32;
        const int prow = g_perm[i0 + (tid >> 3)];     // fixed Zi row per thread
        const int un0  = tid & 7;

        auto load_stage = [&](int c) {
            uint32_t st = stg0 + (uint32_t)(c % NSTAGE) * STAGE_U;
            int k0 = c * KC;
            cp16(st + SW128((uint32_t)(tid * 16)),
                 g_zb + (size_t)prow * FEAT_D + k0 + un0 * 8);
#pragma unroll
            for (int q = 0; q < 4; ++q) {
                int u = tid + q * 256;
                int row = u >> 3, un = u & 7;
                cp16(st + 4096 + SW128((uint32_t)(u * 16)),
                     g_wab + (size_t)row * FEAT_D + k0 + un * 8);
            }
            asm volatile("cp.async.commit_group;" ::: "memory");
        };

        float cg[1][4][4] = {};
        PIPELINE_GEMM(1, STAGE_U, 4096)

        const int g  = lane >> 2;
        const int tg = lane & 3;
        {
            int r0 = i0 + wm * 16 + g;
#pragma unroll
            for (int nt = 0; nt < 4; ++nt) {
                int a0 = wn * 32 + nt * 8 + tg * 2;
#pragma unroll
                for (int h = 0; h < 2; ++h) {
                    g_U[(size_t)(a0 + h) * BATCH_N + r0]     = cg[0][nt][h];
                    g_U[(size_t)(a0 + h) * BATCH_N + r0 + 8] = cg[0][nt][2 + h];
                }
            }
        }
        __syncthreads();
        if (tid == 0) {
            __threadfence();
            atomicAdd(&g_cnt_u, 1);
        }
        return;
    }

    // ---------- main tile: 64 x 128 G + fused epilogue ----------
    float* s_sqi  = (float*)(ab);
    int*   s_agi  = (int*)(ab + 256);
    float* s_sqj  = (float*)(ab + 512);
    float* s_dwj  = (float*)(ab + 1024);
    int*   s_agej = (int*)(ab + 1536);
    float* s_red  = (float*)(ab + META);

    int b = blockIdx.x - NU;
    int J = (int)((sqrtf(4.0f * (float)b + 1.0f) - 1.0f) * 0.5f);
    while ((J + 1) * (J + 1) + (J + 1) <= b) ++J;
    while (J * J + J > b) --J;
    const int I  = b - (J * J + J);
    const int i0 = I * TI;
    const int j0 = J * TJ;

    // cached perm rows for the loader (fixed across chunks)
    const int pi0 = g_perm[i0 + (tid >> 3)];
    const int pi1 = g_perm[i0 + 32 + (tid >> 3)];
    int pj[4];
#pragma unroll
    for (int q = 0; q < 4; ++q) pj[q] = g_perm[j0 + ((tid + q * 256) >> 3)];
    const int un0 = tid & 7;

    if (tid < 128) {
        int jp = g_perm[j0 + tid];
        s_agej[tid] = g_ages[j0 + tid];
        s_sqj[tid]  = g_sq[jp];
    } else if (tid < 192) {
        int r = tid - 128;
        s_sqi[r] = g_sq[g_perm[i0 + r]];
        s_agi[r] = g_ages[i0 + r];
    }

    auto load_stage = [&](int c) {
        uint32_t st = stg0 + (uint32_t)(c % NSTAGE) * STAGE_MAIN;
        int k0 = c * KC;
        cp16(st + SW128((uint32_t)(tid * 16)),
             g_zb + (size_t)pi0 * FEAT_D + k0 + un0 * 8);
        cp16(st + SW128((uint32_t)((tid + 256) * 16)),
             g_zb + (size_t)pi1 * FEAT_D + k0 + un0 * 8);
#pragma unroll
        for (int q = 0; q < 4; ++q) {
            int u = tid + q * 256;
            cp16(st + 8192 + SW128((uint32_t)(u * 16)),
                 g_zb + (size_t)pj[q] * FEAT_D + k0 + un0 * 8);
        }
        asm volatile("cp.async.commit_group;" ::: "memory");
    };

    float cg[2][4][4] = {};
    PIPELINE_GEMM(2, STAGE_MAIN, 8192)

    // ---- gate on U completion ----
    if (tid == 0) {
        while (*(volatile int*)&g_cnt_u < NU) {}
    }
    __syncthreads();
    if (tid < 128) {
        s_dwj[tid] = g_U[(size_t)s_agej[tid] * BATCH_N + j0 + tid];
    }
    __syncthreads();

    // ---- epilogue ----
    const int g  = lane >> 2;
    const int tg = lane & 3;
    float sqi0[2], sqi1[2];
    int   agi0[2], agi1[2];
#pragma unroll
    for (int mt = 0; mt < 2; ++mt) {
        int r0 = wm * 32 + mt * 16 + g;
        sqi0[mt] = s_sqi[r0];      agi0[mt] = s_agi[r0];
        sqi1[mt] = s_sqi[r0 + 8];  agi1[mt] = s_agi[r0 + 8];
    }

    float lsum = 0.f;
#pragma unroll
    for (int nt = 0; nt < 4; ++nt) {
#pragma unroll
        for (int h = 0; h < 2; ++h) {
            int cj = wn * 32 + nt * 8 + tg * 2 + h;
            int   agj = s_agej[cj];
            float sqj = s_sqj[cj], dwj = s_dwj[cj];
            const float* Up = g_U + (size_t)agj * BATCH_N + i0 + wm * 32 + g;
#pragma unroll
            for (int mt = 0; mt < 2; ++mt) {
                if (agi0[mt] < agj) {
                    float G  = cg[mt][nt][h];
                    float d2 = fmaxf(sqi0[mt] + sqj - 2.f * G, 0.f);
                    float x  = __fdividef((Up[mt * 16] - dwj) * 10.0f, sqrtf(d2) + EPS_F);
                    lsum += fmaxf(x, 0.f) + __logf(1.f + __expf(-fabsf(x)));
                }
                if (agi1[mt] < agj) {
                    float G  = cg[mt][nt][2 + h];
                    float d2 = fmaxf(sqi1[mt] + sqj - 2.f * G, 0.f);
                    float x  = __fdividef((Up[mt * 16 + 8] - dwj) * 10.0f, sqrtf(d2) + EPS_F);
                    lsum += fmaxf(x, 0.f) + __logf(1.f + __expf(-fabsf(x)));
                }
            }
        }
    }

    __syncthreads();
    s_red[tid] = lsum;
    __syncthreads();
#pragma unroll
    for (int s = 128; s > 0; s >>= 1) {
        if (tid < s) s_red[tid] += s_red[tid + s];
        __syncthreads();
    }
    if (tid == 0) {
        atomicAdd(&g_acc, (double)s_red[0]);
        __threadfence();
        int n = atomicAdd(&g_cnt, 1);
        if (n == NPAIR - 1) {
            __threadfence();
            double v = atomicAdd(&g_acc, 0.0);
            out[0] = (float)(v / ((double)BATCH_N * (double)(BATCH_N - 1)));
        }
    }
}

extern "C" void kernel_launch(void* const* d_in, const int* in_sizes, int n_in,
                              void* d_out, int out_size) {
    const float* z       = (const float*)d_in[0];
    const void*  ages    = d_in[1];
    const float* proxies = (const float*)d_in[2];
    float* out = (float*)d_out;

    cudaFuncSetAttribute(k_main, cudaFuncAttributeMaxDynamicSharedMemorySize, SMEM_MAIN);

    k_pre<<<1 + NW + NPREP, 256>>>(z, ages, proxies);
    k_main<<<NU + NPAIR, 256, SMEM_MAIN>>>(out);
}